// round 8
// baseline (speedup 1.0000x reference)
#include <cuda_runtime.h>
#include <cuda_bf16.h>
#include <cstdint>

#define NV  4096
#define NBW 64

__device__ int   g_deg[NV];
__device__ int   g_nbr[NV*NBW];
__device__ __align__(16) __nv_bfloat16 g_a2d[(size_t)NV*NV];   // dense a2, bf16 exact
__device__ __align__(16) float g_seg[(size_t)NV*32*8];         // per-row per-128-seg top8
__device__ float g_feats[NV*16];
__device__ float g_x0[NV*64];
__device__ float g_x1[NV*64];

__device__ __forceinline__ uint32_t smem_u32(const void* p) {
    uint32_t a;
    asm("{ .reg .u64 t; cvta.to.shared.u64 t, %1; cvt.u32.u64 %0, t; }" : "=r"(a) : "l"(p));
    return a;
}

// ---------------- K0: adjacency lists (ordered) ----------------
__global__ void k_nbr(const float* __restrict__ adj) {
    int v = blockIdx.x, tid = threadIdx.x;     // 128 threads
    __shared__ int sc[128];
    const float* row = adj + (size_t)v * NV;
    int base = tid * 32, cnt = 0;
#pragma unroll 8
    for (int j = 0; j < 32; ++j) cnt += (row[base + j] > 0.5f) ? 1 : 0;
    sc[tid] = cnt; __syncthreads();
    for (int off = 1; off < 128; off <<= 1) {
        int x = (tid >= off) ? sc[tid - off] : 0;
        __syncthreads();
        sc[tid] += x;
        __syncthreads();
    }
    int pos = sc[tid] - cnt;
    for (int j = 0; j < 32; ++j)
        if (row[base + j] > 0.5f) { if (pos < NBW) g_nbr[v*NBW + pos] = base + j; ++pos; }
    if (tid == 127) g_deg[v] = min(sc[127], NBW - 1);
}

// ---------------- K1: cr_feat + degree_feat, masks from nbr lists + smem map ----
__global__ void k_cr(void) {
    int w = threadIdx.x >> 5, lane = threadIdx.x & 31;
    int v = blockIdx.x * 4 + w;
    __shared__ unsigned char pos[4][NV];
    __shared__ int memb[4][64];
    __shared__ unsigned long long msk[4][64];
    for (int i = lane; i < NV / 4; i += 32) ((uint32_t*)pos[w])[i] = 0;
    int deg = g_deg[v];
    int s = deg + 1;
    for (int i = lane; i < 64; i += 32) {
        int g = v;
        if (i >= 1 && i < s) g = g_nbr[v*NBW + i - 1];
        memb[w][i] = g;
    }
    __syncwarp();
    for (int i = lane; i < s; i += 32) pos[w][memb[w][i]] = (unsigned char)(i + 1);
    __syncwarp();
    for (int half = 0; half < 2; ++half) {
        int i = lane + 32 * half;
        unsigned long long m = 0;
        if (i < s) {
            int u = memb[w][i];
            int du = g_deg[u];
            const int* nl = g_nbr + u * NBW;
            for (int t = 0; t < du; ++t) {
                int p = pos[w][nl[t]];
                if (p) m |= 1ull << (p - 1);
            }
        }
        msk[w][i] = m;
    }
    __syncwarp();
    unsigned long long m0 = msk[w][0];
    int E2 = 0, Wi = 0, T6 = 0;
    for (int half = 0; half < 2; ++half) {
        int i = lane + 32 * half;
        if (i < s) {
            unsigned long long mi = msk[w][i];
            int D = __popcll(m0 & mi) + (i > 0 ? 1 : 0);
            E2 += D;
            Wi += D * (D - 1) / 2;
            unsigned long long mm = mi;
            while (mm) {
                int j = __ffsll((long long)mm) - 1;
                mm &= (mm - 1);
                T6 += __popcll(mi & msk[w][j]);
            }
        }
    }
    for (int o = 16; o; o >>= 1) {
        E2 += __shfl_down_sync(0xffffffffu, E2, o);
        Wi += __shfl_down_sync(0xffffffffu, Wi, o);
        T6 += __shfl_down_sync(0xffffffffu, T6, o);
    }
    if (lane == 0) {
        float kf = (float)s;
        float T  = (float)(T6 / 6);
        float f3 = T;
        float f2 = (float)Wi - 3.0f * T;
        float E  = 0.5f * (float)E2;
        float f1 = E * (kf - 2.0f) - 2.0f * f2 - 3.0f * f3;
        int   totn = s * (s - 1) * (s - 2) / 6;
        float f0 = (float)totn - f1 - f2 - f3;
        if (s < 3) { f0 = f1 = f2 = f3 = 0.0f; }
        float inv = 1.0f / ((f0 + f1 + f2 + f3) + 1e-10f);
        float* fp = g_feats + v * 16;
        fp[0] = f0 * inv; fp[1] = f1 * inv; fp[2] = f2 * inv; fp[3] = f3 * inv;
        float d = (float)deg;
        fp[12] = d; fp[13] = d * d; fp[14] = d; fp[15] = 0.0f;
    }
}

// ---------------- K2: dense a2 rows in bf16 (exact: values <= 63) ----------------
__global__ void k_a2(void) {
    int v = blockIdx.x, tid = threadIdx.x;   // 256 threads
    __shared__ int cnt[NV];
    for (int c = tid; c < NV; c += 256) cnt[c] = 0;
    __syncthreads();
    int dv = g_deg[v];
    for (int ui = tid; ui < dv; ui += 256) {
        int u = g_nbr[v*NBW + ui];
        int du = g_deg[u];
        const int* nl = g_nbr + u * NBW;
        for (int t = 0; t < du; ++t) atomicAdd(&cnt[nl[t]], 1);
    }
    __syncthreads();
    __nv_bfloat162* dst = (__nv_bfloat162*)(g_a2d + (size_t)v * NV);
    for (int p = tid; p < NV / 2; p += 256)
        dst[p] = __floats2bfloat162_rn((float)cnt[2*p], (float)cnt[2*p + 1]);
}

// ---------------- K3: a4 = a2 @ a2 via HMMA + ldmatrix, fused segment top-8 ----
#define RSB 144                    /* smem row stride bytes: 64 bf16 + 8 pad */
#define TILEB (128*RSB)            /* 18432 B per tile */
#define STAGEB (2*TILEB)           /* A + B per stage */
#define SLD 132                    /* epilogue smem row stride (floats) */

__device__ __forceinline__ void cp16(uint32_t s, const void* g) {
    asm volatile("cp.async.cg.shared.global [%0], [%1], 16;" :: "r"(s), "l"(g) : "memory");
}
__device__ __forceinline__ void ldsm4(uint32_t& r0, uint32_t& r1, uint32_t& r2, uint32_t& r3,
                                      uint32_t addr) {
    asm volatile("ldmatrix.sync.aligned.m8n8.x4.shared.b16 {%0,%1,%2,%3}, [%4];"
                 : "=r"(r0), "=r"(r1), "=r"(r2), "=r"(r3) : "r"(addr));
}
// insert v into descending top-8 list b[]
__device__ __forceinline__ void ins8(float* b, float v) {
    if (v > b[7]) {
        b[7] = v;
#pragma unroll
        for (int j = 7; j >= 1; --j) {
            if (b[j] > b[j-1]) { float t = b[j]; b[j] = b[j-1]; b[j-1] = t; }
        }
    }
}

__global__ void __launch_bounds__(256, 2) k_gemm(void) {
    extern __shared__ __align__(16) char sm[];
    uint32_t sb = smem_u32(sm);
    int tid = threadIdx.x, lane = tid & 31, wid = tid >> 5;
    int warp_m = wid >> 1, warp_n = wid & 1;

    // decode upper-triangular block pair
    int x = blockIdx.x, bm = 0;
    while (x >= 32 - bm) { x -= (32 - bm); ++bm; }
    int bn = bm + x;
    int m0 = bm * 128, n0 = bn * 128;

    const __nv_bfloat16* A2 = g_a2d;

    float acc[2][8][4];
#pragma unroll
    for (int i = 0; i < 2; ++i)
#pragma unroll
        for (int j = 0; j < 8; ++j)
#pragma unroll
            for (int q = 0; q < 4; ++q) acc[i][j][q] = 0.0f;

    auto load_stage = [&](int kc, int buf) {
        uint32_t st = sb + (uint32_t)buf * STAGEB;
        size_t kb = (size_t)kc * 64;
#pragma unroll
        for (int i = 0; i < 4; ++i) {
            int idx = i * 256 + tid;          // 0..1023
            int r = idx >> 3, c16 = idx & 7;
            const void* ga = A2 + (size_t)(m0 + r) * NV + kb + c16 * 8;
            const void* gb = A2 + (size_t)(n0 + r) * NV + kb + c16 * 8;
            cp16(st + r * RSB + c16 * 16, ga);
            cp16(st + TILEB + r * RSB + c16 * 16, gb);
        }
        asm volatile("cp.async.commit_group;" ::: "memory");
    };

    load_stage(0, 0);

    uint32_t aL = sb + (uint32_t)(warp_m * 32 + (lane & 15)) * RSB + (uint32_t)(lane >> 4) * 16;
    uint32_t bL = sb + TILEB
                + (uint32_t)(warp_n * 64 + ((lane >> 4) & 1) * 8 + (lane & 7)) * RSB
                + (uint32_t)((lane >> 3) & 1) * 16;

    for (int c = 0; c < 64; ++c) {
        int buf = c & 1;
        if (c + 1 < 64) {
            load_stage(c + 1, buf ^ 1);
            asm volatile("cp.async.wait_group 1;" ::: "memory");
        } else {
            asm volatile("cp.async.wait_group 0;" ::: "memory");
        }
        __syncthreads();
        uint32_t off = (uint32_t)buf * STAGEB;
#pragma unroll
        for (int k16 = 0; k16 < 4; ++k16) {
            uint32_t koff = off + (uint32_t)k16 * 32;
            uint32_t a[2][4];
            ldsm4(a[0][0], a[0][1], a[0][2], a[0][3], aL + koff);
            ldsm4(a[1][0], a[1][1], a[1][2], a[1][3], aL + koff + 16u * RSB);
            uint32_t b[8][2];
#pragma unroll
            for (int j = 0; j < 4; ++j)
                ldsm4(b[2*j][0], b[2*j][1], b[2*j+1][0], b[2*j+1][1],
                      bL + koff + (uint32_t)j * (16u * RSB));
#pragma unroll
            for (int nt = 0; nt < 8; ++nt) {
#pragma unroll
                for (int mt = 0; mt < 2; ++mt) {
                    asm volatile(
                        "mma.sync.aligned.m16n8k16.row.col.f32.bf16.bf16.f32 "
                        "{%0,%1,%2,%3}, {%4,%5,%6,%7}, {%8,%9}, {%0,%1,%2,%3};"
                        : "+f"(acc[mt][nt][0]), "+f"(acc[mt][nt][1]),
                          "+f"(acc[mt][nt][2]), "+f"(acc[mt][nt][3])
                        : "r"(a[mt][0]), "r"(a[mt][1]), "r"(a[mt][2]), "r"(a[mt][3]),
                          "r"(b[nt][0]), "r"(b[nt][1]));
                }
            }
        }
        __syncthreads();
    }

    // ---- fused epilogue: block -> smem, per-row & per-col segment top-8 ----
    float* S = (float*)sm;                    // 128 x SLD floats = 67584 B
    int g = lane >> 2, t = lane & 3;
#pragma unroll
    for (int mt = 0; mt < 2; ++mt) {
        int row = warp_m * 32 + mt * 16 + g;
#pragma unroll
        for (int nt = 0; nt < 8; ++nt) {
            int col = warp_n * 64 + nt * 8 + 2 * t;
            S[row * SLD + col]           = acc[mt][nt][0];
            S[row * SLD + col + 1]       = acc[mt][nt][1];
            S[(row + 8) * SLD + col]     = acc[mt][nt][2];
            S[(row + 8) * SLD + col + 1] = acc[mt][nt][3];
        }
    }
    __syncthreads();

    // pass 1: rows of this block -> segment bn of rows m0+r
    {
        int r = tid >> 1, half = tid & 1;
        const float* Sp = S + r * SLD + half * 64;
        float b8[8];
#pragma unroll
        for (int j = 0; j < 8; ++j) b8[j] = -1.0f;
        for (int i = 0; i < 64; ++i) ins8(b8, Sp[i]);
        float o8[8];
        {
            float other[8];
#pragma unroll
            for (int j = 0; j < 8; ++j)
                other[j] = __shfl_xor_sync(0xffffffffu, b8[j], 1);
            int ia = 0, ib = 0;
#pragma unroll
            for (int k = 0; k < 8; ++k) {
                float va = b8[ia], vb = other[ib];
                if (va >= vb) { o8[k] = va; ++ia; } else { o8[k] = vb; ++ib; }
            }
        }
        if (half == 0) {
            float* dst = g_seg + ((size_t)(m0 + r) * 32 + bn) * 8;
            *(float4*)dst       = make_float4(o8[0], o8[1], o8[2], o8[3]);
            *(float4*)(dst + 4) = make_float4(o8[4], o8[5], o8[6], o8[7]);
        }
    }

    // pass 2 (off-diagonal): columns -> segment bm of rows n0+c
    if (bm != bn) {
        int cc = tid >> 1, half = tid & 1;
        const float* Sp = S + half * 64 * SLD + cc;
        float b8[8];
#pragma unroll
        for (int j = 0; j < 8; ++j) b8[j] = -1.0f;
        for (int i = 0; i < 64; ++i) ins8(b8, Sp[i * SLD]);
        float o8[8];
        {
            float other[8];
#pragma unroll
            for (int j = 0; j < 8; ++j)
                other[j] = __shfl_xor_sync(0xffffffffu, b8[j], 1);
            int ia = 0, ib = 0;
#pragma unroll
            for (int k = 0; k < 8; ++k) {
                float va = b8[ia], vb = other[ib];
                if (va >= vb) { o8[k] = va; ++ia; } else { o8[k] = vb; ++ib; }
            }
        }
        if (half == 0) {
            float* dst = g_seg + ((size_t)(n0 + cc) * 32 + bm) * 8;
            *(float4*)dst       = make_float4(o8[0], o8[1], o8[2], o8[3]);
            *(float4*)(dst + 4) = make_float4(o8[4], o8[5], o8[6], o8[7]);
        }
    }
}

// ---------------- K3b: final top-8 per row from 32x8 candidates ----------------
__global__ void k_top8r(void) {
    int wid = threadIdx.x >> 5, lane = threadIdx.x & 31;  // 256 thr: 8 rows/block
    int v = blockIdx.x * 8 + wid;
    const float4* p = (const float4*)(g_seg + (size_t)v * 256);
    float4 c0 = p[lane * 2], c1 = p[lane * 2 + 1];
    float cand[8] = {c0.x, c0.y, c0.z, c0.w, c1.x, c1.y, c1.z, c1.w};
    // clamp sentinels: a4 >= 0, so negatives only arise from short segments
#pragma unroll
    for (int s = 0; s < 8; ++s) cand[s] = fmaxf(cand[s], 0.0f);
    for (int r = 0; r < 8; ++r) {
        unsigned long long best = 0;
#pragma unroll
        for (int s = 0; s < 8; ++s) {
            unsigned long long cd =
                ((unsigned long long)__float_as_uint(cand[s]) << 32) | (unsigned)(lane * 8 + s);
            if (cd > best) best = cd;
        }
#pragma unroll
        for (int o = 16; o; o >>= 1) {
            unsigned long long tt = __shfl_xor_sync(0xffffffffu, best, o);
            if (tt > best) best = tt;
        }
        unsigned widx = (unsigned)(best & 0xffffffffu);
        if ((int)(widx >> 3) == lane) cand[widx & 7] = 0.0f;   // 0-bits sort to bottom
        if (lane == 0) g_feats[v*16 + 4 + r] = __uint_as_float((unsigned)(best >> 32));
    }
}

// ---------------- K4: embed ----------------
__global__ void k_embed(const float* __restrict__ ew, const float* __restrict__ eb) {
    int w = threadIdx.x >> 5, lane = threadIdx.x & 31;
    int v = blockIdx.x * 8 + w;
    int c = lane * 2;
    float a0 = eb[c], a1 = eb[c + 1];
    const float* fp = g_feats + v * 16;
#pragma unroll
    for (int t = 0; t < 15; ++t) {
        float fv = fp[t];
        a0 += fv * ew[t*64 + c];
        a1 += fv * ew[t*64 + c + 1];
    }
    g_x0[v*64 + c] = a0;
    g_x0[v*64 + c + 1] = a1;
}

// ---------------- K5: one GIN layer ----------------
__global__ void k_layer(int src,
                        const float* __restrict__ w1, const float* __restrict__ b1,
                        const float* __restrict__ w2, const float* __restrict__ b2,
                        const float* __restrict__ epsp) {
    __shared__ float w1s[4096], w2s[4096], b1s[64], b2s[64], hb[8][64];
    int tid = threadIdx.x;                   // 256 threads, 8 rows/block
    const float* xin = src ? g_x1 : g_x0;
    float*       xout = src ? g_x0 : g_x1;
    for (int i = tid; i < 4096; i += 256) { w1s[i] = w1[i]; w2s[i] = w2[i]; }
    if (tid < 64) { b1s[tid] = b1[tid]; b2s[tid] = b2[tid]; }
    __syncthreads();
    int w = tid >> 5, lane = tid & 31;
    int v = blockIdx.x * 8 + w;
    int c = lane * 2;
    float ev = 1.0f + epsp[0];
    float h0 = ev * xin[v*64 + c], h1 = ev * xin[v*64 + c + 1];
    int dv = g_deg[v];
    const int* nl = g_nbr + v * NBW;
    for (int t = 0; t < dv; ++t) {
        const float* xr = xin + (size_t)nl[t] * 64;
        h0 += xr[c]; h1 += xr[c + 1];
    }
    hb[w][c] = h0; hb[w][c + 1] = h1;
    __syncwarp();
    float a0 = b1s[c], a1 = b1s[c + 1];
#pragma unroll 8
    for (int k = 0; k < 64; ++k) {
        float hk = hb[w][k];
        a0 += hk * w1s[k*64 + c];
        a1 += hk * w1s[k*64 + c + 1];
    }
    a0 = fmaxf(a0, 0.0f); a1 = fmaxf(a1, 0.0f);
    __syncwarp();
    hb[w][c] = a0; hb[w][c + 1] = a1;
    __syncwarp();
    float o0 = b2s[c], o1 = b2s[c + 1];
#pragma unroll 8
    for (int k = 0; k < 64; ++k) {
        float hk = hb[w][k];
        o0 += hk * w2s[k*64 + c];
        o1 += hk * w2s[k*64 + c + 1];
    }
    xout[v*64 + c] = o0;
    xout[v*64 + c + 1] = o1;
}

// ---------------- K6: deterministic column sum ----------------
__global__ void k_colsum(float* __restrict__ out) {
    int c = blockIdx.x, tid = threadIdx.x;
    __shared__ float sp[256];
    float a = 0.0f;
    for (int v = tid; v < NV; v += 256) a += g_x1[v*64 + c];
    sp[tid] = a; __syncthreads();
    for (int o = 128; o; o >>= 1) { if (tid < o) sp[tid] += sp[tid + o]; __syncthreads(); }
    if (tid == 0) out[c] = sp[0];
}

extern "C" void kernel_launch(void* const* d_in, const int* in_sizes, int n_in,
                              void* d_out, int out_size) {
    const float* adj = (const float*)d_in[0];
    const float* ew  = (const float*)d_in[1];
    const float* eb  = (const float*)d_in[2];
    const float* w1  = (const float*)d_in[3];
    const float* b1  = (const float*)d_in[4];
    const float* w2  = (const float*)d_in[5];
    const float* b2  = (const float*)d_in[6];
    const float* eps = (const float*)d_in[7];
    float* out = (float*)d_out;
    (void)in_sizes; (void)n_in; (void)out_size;

    cudaFuncSetAttribute(k_gemm, cudaFuncAttributeMaxDynamicSharedMemorySize, 2 * STAGEB);

    k_nbr<<<NV, 128>>>(adj);
    k_cr<<<NV / 4, 128>>>();
    k_a2<<<NV, 256>>>();
    k_gemm<<<528, 256, 2 * STAGEB>>>();
    k_top8r<<<NV / 8, 256>>>();
    k_embed<<<NV / 8, 256>>>(ew, eb);
    k_layer<<<NV / 8, 256>>>(0, w1 + 0*4096, b1 + 0*64, w2 + 0*4096, b2 + 0*64, eps + 0);
    k_layer<<<NV / 8, 256>>>(1, w1 + 1*4096, b1 + 1*64, w2 + 1*4096, b2 + 1*64, eps + 1);
    k_layer<<<NV / 8, 256>>>(0, w1 + 2*4096, b1 + 2*64, w2 + 2*4096, b2 + 2*64, eps + 2);
    k_colsum<<<64, 256>>>(out);
}

// round 9
// speedup vs baseline: 1.2618x; 1.2618x over previous
#include <cuda_runtime.h>
#include <cuda_bf16.h>
#include <cstdint>

#define NV  4096
#define NBW 64

__device__ int   g_deg[NV];
__device__ int   g_nbr[NV*NBW];
__device__ __align__(16) __nv_bfloat16 g_a2d[(size_t)NV*NV];   // dense a2, bf16 exact
__device__ __align__(16) float         g_a4[(size_t)NV*NV];    // dense a4 fp32 exact
__device__ float g_feats[NV*16];
__device__ float g_x0[NV*64];
__device__ float g_x1[NV*64];

__device__ __forceinline__ uint32_t smem_u32(const void* p) {
    uint32_t a;
    asm("{ .reg .u64 t; cvta.to.shared.u64 t, %1; cvt.u32.u64 %0, t; }" : "=r"(a) : "l"(p));
    return a;
}

// ---------------- K0: adjacency lists (ordered, coalesced + ballot) ----------------
__global__ void k_nbr(const float* __restrict__ adj) {
    int v = blockIdx.x, tid = threadIdx.x;     // 128 threads
    int w = tid >> 5, lane = tid & 31;
    __shared__ int wc[4];
    const float* row = adj + (size_t)v * NV;
    int cbase = w * 1024;
    int cnt = 0;
#pragma unroll 4
    for (int it = 0; it < 32; ++it) {
        float x = row[cbase + it * 32 + lane];
        unsigned m = __ballot_sync(0xffffffffu, x > 0.5f);
        cnt += __popc(m);
    }
    if (lane == 0) wc[w] = cnt;
    __syncthreads();
    int base = 0;
#pragma unroll
    for (int i = 0; i < 4; ++i) if (i < w) base += wc[i];
    int total = wc[0] + wc[1] + wc[2] + wc[3];
    int pos = base;
    unsigned ltmask = (lane == 31) ? 0x7fffffffu : ((1u << lane) - 1u);
    for (int it = 0; it < 32; ++it) {
        float x = row[cbase + it * 32 + lane];    // L1-hot second pass
        bool p = x > 0.5f;
        unsigned m = __ballot_sync(0xffffffffu, p);
        if (p) {
            int mypos = pos + __popc(m & ltmask);
            if (mypos < NBW) g_nbr[v*NBW + mypos] = cbase + it * 32 + lane;
        }
        pos += __popc(m);
    }
    if (tid == 0) g_deg[v] = min(total, NBW - 1);
}

// ---------------- K1: cr_feat + degree_feat, masks from nbr lists + smem map ----
__global__ void k_cr(void) {
    int w = threadIdx.x >> 5, lane = threadIdx.x & 31;
    int v = blockIdx.x * 4 + w;
    __shared__ unsigned char pos[4][NV];
    __shared__ int memb[4][64];
    __shared__ unsigned long long msk[4][64];
    for (int i = lane; i < NV / 4; i += 32) ((uint32_t*)pos[w])[i] = 0;
    int deg = g_deg[v];
    int s = deg + 1;
    for (int i = lane; i < 64; i += 32) {
        int g = v;
        if (i >= 1 && i < s) g = g_nbr[v*NBW + i - 1];
        memb[w][i] = g;
    }
    __syncwarp();
    for (int i = lane; i < s; i += 32) pos[w][memb[w][i]] = (unsigned char)(i + 1);
    __syncwarp();
    for (int half = 0; half < 2; ++half) {
        int i = lane + 32 * half;
        unsigned long long m = 0;
        if (i < s) {
            int u = memb[w][i];
            int du = g_deg[u];
            const int* nl = g_nbr + u * NBW;
            for (int t = 0; t < du; ++t) {
                int p = pos[w][nl[t]];
                if (p) m |= 1ull << (p - 1);
            }
        }
        msk[w][i] = m;
    }
    __syncwarp();
    unsigned long long m0 = msk[w][0];
    int E2 = 0, Wi = 0, T6 = 0;
    for (int half = 0; half < 2; ++half) {
        int i = lane + 32 * half;
        if (i < s) {
            unsigned long long mi = msk[w][i];
            int D = __popcll(m0 & mi) + (i > 0 ? 1 : 0);
            E2 += D;
            Wi += D * (D - 1) / 2;
            unsigned long long mm = mi;
            while (mm) {
                int j = __ffsll((long long)mm) - 1;
                mm &= (mm - 1);
                T6 += __popcll(mi & msk[w][j]);
            }
        }
    }
    for (int o = 16; o; o >>= 1) {
        E2 += __shfl_down_sync(0xffffffffu, E2, o);
        Wi += __shfl_down_sync(0xffffffffu, Wi, o);
        T6 += __shfl_down_sync(0xffffffffu, T6, o);
    }
    if (lane == 0) {
        float kf = (float)s;
        float T  = (float)(T6 / 6);
        float f3 = T;
        float f2 = (float)Wi - 3.0f * T;
        float E  = 0.5f * (float)E2;
        float f1 = E * (kf - 2.0f) - 2.0f * f2 - 3.0f * f3;
        int   totn = s * (s - 1) * (s - 2) / 6;
        float f0 = (float)totn - f1 - f2 - f3;
        if (s < 3) { f0 = f1 = f2 = f3 = 0.0f; }
        float inv = 1.0f / ((f0 + f1 + f2 + f3) + 1e-10f);
        float* fp = g_feats + v * 16;
        fp[0] = f0 * inv; fp[1] = f1 * inv; fp[2] = f2 * inv; fp[3] = f3 * inv;
        float d = (float)deg;
        fp[12] = d; fp[13] = d * d; fp[14] = d; fp[15] = 0.0f;
    }
}

// ---------------- K2: dense a2 rows in bf16 (exact: values <= 63) ----------------
__global__ void k_a2(void) {
    int v = blockIdx.x, tid = threadIdx.x;   // 256 threads
    __shared__ int cnt[NV];
    for (int c = tid; c < NV; c += 256) cnt[c] = 0;
    __syncthreads();
    int dv = g_deg[v];
    for (int ui = tid; ui < dv; ui += 256) {
        int u = g_nbr[v*NBW + ui];
        int du = g_deg[u];
        const int* nl = g_nbr + u * NBW;
        for (int t = 0; t < du; ++t) atomicAdd(&cnt[nl[t]], 1);
    }
    __syncthreads();
    __nv_bfloat162* dst = (__nv_bfloat162*)(g_a2d + (size_t)v * NV);
    for (int p = tid; p < NV / 2; p += 256)
        dst[p] = __floats2bfloat162_rn((float)cnt[2*p], (float)cnt[2*p + 1]);
}

// ---------------- K3: a4 = a2 @ a2 via HMMA + ldmatrix, symmetric blocks ----
#define RSB 144                    /* smem row stride bytes: 64 bf16 + 8 pad */
#define TILEB (128*RSB)            /* 18432 B per tile */
#define STAGEB (2*TILEB)           /* A + B per stage */

__device__ __forceinline__ void cp16(uint32_t s, const void* g) {
    asm volatile("cp.async.cg.shared.global [%0], [%1], 16;" :: "r"(s), "l"(g) : "memory");
}
__device__ __forceinline__ void ldsm4(uint32_t& r0, uint32_t& r1, uint32_t& r2, uint32_t& r3,
                                      uint32_t addr) {
    asm volatile("ldmatrix.sync.aligned.m8n8.x4.shared.b16 {%0,%1,%2,%3}, [%4];"
                 : "=r"(r0), "=r"(r1), "=r"(r2), "=r"(r3) : "r"(addr));
}

__global__ void __launch_bounds__(256, 2) k_gemm(void) {
    extern __shared__ __align__(16) char sm[];
    uint32_t sb = smem_u32(sm);
    int tid = threadIdx.x, lane = tid & 31, wid = tid >> 5;
    int warp_m = wid >> 1, warp_n = wid & 1;

    // decode upper-triangular block pair
    int x = blockIdx.x, bm = 0;
    while (x >= 32 - bm) { x -= (32 - bm); ++bm; }
    int bn = bm + x;
    int m0 = bm * 128, n0 = bn * 128;

    const __nv_bfloat16* A2 = g_a2d;

    float acc[2][8][4];
#pragma unroll
    for (int i = 0; i < 2; ++i)
#pragma unroll
        for (int j = 0; j < 8; ++j)
#pragma unroll
            for (int q = 0; q < 4; ++q) acc[i][j][q] = 0.0f;

    auto load_stage = [&](int kc, int buf) {
        uint32_t st = sb + (uint32_t)buf * STAGEB;
        size_t kb = (size_t)kc * 64;
#pragma unroll
        for (int i = 0; i < 4; ++i) {
            int idx = i * 256 + tid;          // 0..1023
            int r = idx >> 3, c16 = idx & 7;
            const void* ga = A2 + (size_t)(m0 + r) * NV + kb + c16 * 8;
            const void* gb = A2 + (size_t)(n0 + r) * NV + kb + c16 * 8;
            cp16(st + r * RSB + c16 * 16, ga);
            cp16(st + TILEB + r * RSB + c16 * 16, gb);
        }
        asm volatile("cp.async.commit_group;" ::: "memory");
    };

    load_stage(0, 0);

    uint32_t aL = sb + (uint32_t)(warp_m * 32 + (lane & 15)) * RSB + (uint32_t)(lane >> 4) * 16;
    uint32_t bL = sb + TILEB
                + (uint32_t)(warp_n * 64 + ((lane >> 4) & 1) * 8 + (lane & 7)) * RSB
                + (uint32_t)((lane >> 3) & 1) * 16;

    for (int c = 0; c < 64; ++c) {
        int buf = c & 1;
        if (c + 1 < 64) {
            load_stage(c + 1, buf ^ 1);
            asm volatile("cp.async.wait_group 1;" ::: "memory");
        } else {
            asm volatile("cp.async.wait_group 0;" ::: "memory");
        }
        __syncthreads();
        uint32_t off = (uint32_t)buf * STAGEB;
#pragma unroll
        for (int k16 = 0; k16 < 4; ++k16) {
            uint32_t koff = off + (uint32_t)k16 * 32;
            uint32_t a[2][4];
            ldsm4(a[0][0], a[0][1], a[0][2], a[0][3], aL + koff);
            ldsm4(a[1][0], a[1][1], a[1][2], a[1][3], aL + koff + 16u * RSB);
            uint32_t b[8][2];
#pragma unroll
            for (int j = 0; j < 4; ++j)
                ldsm4(b[2*j][0], b[2*j][1], b[2*j+1][0], b[2*j+1][1],
                      bL + koff + (uint32_t)j * (16u * RSB));
#pragma unroll
            for (int nt = 0; nt < 8; ++nt) {
#pragma unroll
                for (int mt = 0; mt < 2; ++mt) {
                    asm volatile(
                        "mma.sync.aligned.m16n8k16.row.col.f32.bf16.bf16.f32 "
                        "{%0,%1,%2,%3}, {%4,%5,%6,%7}, {%8,%9}, {%0,%1,%2,%3};"
                        : "+f"(acc[mt][nt][0]), "+f"(acc[mt][nt][1]),
                          "+f"(acc[mt][nt][2]), "+f"(acc[mt][nt][3])
                        : "r"(a[mt][0]), "r"(a[mt][1]), "r"(a[mt][2]), "r"(a[mt][3]),
                          "r"(b[nt][0]), "r"(b[nt][1]));
                }
            }
        }
        __syncthreads();
    }

    // epilogue: write block, mirror if off-diagonal
    int g = lane >> 2, t = lane & 3;
    float* D = g_a4;
#pragma unroll
    for (int mt = 0; mt < 2; ++mt) {
        int row = m0 + warp_m * 32 + mt * 16 + g;
#pragma unroll
        for (int nt = 0; nt < 8; ++nt) {
            int col = n0 + warp_n * 64 + nt * 8 + 2 * t;
            float2 lo = make_float2(acc[mt][nt][0], acc[mt][nt][1]);
            float2 hi = make_float2(acc[mt][nt][2], acc[mt][nt][3]);
            *(float2*)(D + (size_t)row * NV + col) = lo;
            *(float2*)(D + (size_t)(row + 8) * NV + col) = hi;
            if (bm != bn) {
                D[(size_t)col * NV + row]           = lo.x;
                D[(size_t)(col + 1) * NV + row]     = lo.y;
                D[(size_t)col * NV + row + 8]       = hi.x;
                D[(size_t)(col + 1) * NV + row + 8] = hi.y;
            }
        }
    }
}

// ---------------- K3b: top-8 per row of a4 ----------------
__global__ void k_top8(void) {
    int v = blockIdx.x, tid = threadIdx.x;   // 128 threads
    __shared__ unsigned long long sred[4];
    const float4* row = (const float4*)(g_a4 + (size_t)v * NV);
    float vals[32];
#pragma unroll
    for (int i = 0; i < 8; ++i) {
        float4 f = row[i * 128 + tid];
        vals[i*4+0] = f.x; vals[i*4+1] = f.y; vals[i*4+2] = f.z; vals[i*4+3] = f.w;
    }
    int lane = tid & 31, w = tid >> 5;
    for (int r = 0; r < 8; ++r) {
        unsigned long long best = 0;
#pragma unroll
        for (int s = 0; s < 32; ++s) {
            unsigned long long cand =
                ((unsigned long long)__float_as_uint(vals[s]) << 32) | (unsigned)(tid * 32 + s);
            if (cand > best) best = cand;
        }
        for (int o = 16; o; o >>= 1) {
            unsigned long long t = __shfl_down_sync(0xffffffffu, best, o);
            if (t > best) best = t;
        }
        if (lane == 0) sred[w] = best;
        __syncthreads();
        unsigned long long b0 = sred[0];
        if (sred[1] > b0) b0 = sred[1];
        if (sred[2] > b0) b0 = sred[2];
        if (sred[3] > b0) b0 = sred[3];
        unsigned widx = (unsigned)(b0 & 0xffffffffu);
        if ((int)(widx >> 5) == tid) {
            int slot = widx & 31;
#pragma unroll
            for (int s = 0; s < 32; ++s) if (s == slot) vals[s] = 0.0f;
        }
        if (tid == 0) g_feats[v*16 + 4 + r] = __uint_as_float((unsigned)(b0 >> 32));
        __syncthreads();
    }
}

// ---------------- K4: embed ----------------
__global__ void k_embed(const float* __restrict__ ew, const float* __restrict__ eb) {
    int w = threadIdx.x >> 5, lane = threadIdx.x & 31;
    int v = blockIdx.x * 8 + w;
    int c = lane * 2;
    float a0 = eb[c], a1 = eb[c + 1];
    const float* fp = g_feats + v * 16;
#pragma unroll
    for (int t = 0; t < 15; ++t) {
        float fv = fp[t];
        a0 += fv * ew[t*64 + c];
        a1 += fv * ew[t*64 + c + 1];
    }
    g_x0[v*64 + c] = a0;
    g_x0[v*64 + c + 1] = a1;
}

// ---------------- K5: one GIN layer ----------------
__global__ void k_layer(int src,
                        const float* __restrict__ w1, const float* __restrict__ b1,
                        const float* __restrict__ w2, const float* __restrict__ b2,
                        const float* __restrict__ epsp) {
    __shared__ float w1s[4096], w2s[4096], b1s[64], b2s[64], hb[8][64];
    int tid = threadIdx.x;                   // 256 threads, 8 rows/block
    const float* xin = src ? g_x1 : g_x0;
    float*       xout = src ? g_x0 : g_x1;
    for (int i = tid; i < 4096; i += 256) { w1s[i] = w1[i]; w2s[i] = w2[i]; }
    if (tid < 64) { b1s[tid] = b1[tid]; b2s[tid] = b2[tid]; }
    __syncthreads();
    int w = tid >> 5, lane = tid & 31;
    int v = blockIdx.x * 8 + w;
    int c = lane * 2;
    float ev = 1.0f + epsp[0];
    float h0 = ev * xin[v*64 + c], h1 = ev * xin[v*64 + c + 1];
    int dv = g_deg[v];
    const int* nl = g_nbr + v * NBW;
    for (int t = 0; t < dv; ++t) {
        const float* xr = xin + (size_t)nl[t] * 64;
        h0 += xr[c]; h1 += xr[c + 1];
    }
    hb[w][c] = h0; hb[w][c + 1] = h1;
    __syncwarp();
    float a0 = b1s[c], a1 = b1s[c + 1];
#pragma unroll 8
    for (int k = 0; k < 64; ++k) {
        float hk = hb[w][k];
        a0 += hk * w1s[k*64 + c];
        a1 += hk * w1s[k*64 + c + 1];
    }
    a0 = fmaxf(a0, 0.0f); a1 = fmaxf(a1, 0.0f);
    __syncwarp();
    hb[w][c] = a0; hb[w][c + 1] = a1;
    __syncwarp();
    float o0 = b2s[c], o1 = b2s[c + 1];
#pragma unroll 8
    for (int k = 0; k < 64; ++k) {
        float hk = hb[w][k];
        o0 += hk * w2s[k*64 + c];
        o1 += hk * w2s[k*64 + c + 1];
    }
    xout[v*64 + c] = o0;
    xout[v*64 + c + 1] = o1;
}

// ---------------- K6: deterministic column sum ----------------
__global__ void k_colsum(float* __restrict__ out) {
    int c = blockIdx.x, tid = threadIdx.x;
    __shared__ float sp[256];
    float a = 0.0f;
    for (int v = tid; v < NV; v += 256) a += g_x1[v*64 + c];
    sp[tid] = a; __syncthreads();
    for (int o = 128; o; o >>= 1) { if (tid < o) sp[tid] += sp[tid + o]; __syncthreads(); }
    if (tid == 0) out[c] = sp[0];
}

extern "C" void kernel_launch(void* const* d_in, const int* in_sizes, int n_in,
                              void* d_out, int out_size) {
    const float* adj = (const float*)d_in[0];
    const float* ew  = (const float*)d_in[1];
    const float* eb  = (const float*)d_in[2];
    const float* w1  = (const float*)d_in[3];
    const float* b1  = (const float*)d_in[4];
    const float* w2  = (const float*)d_in[5];
    const float* b2  = (const float*)d_in[6];
    const float* eps = (const float*)d_in[7];
    float* out = (float*)d_out;
    (void)in_sizes; (void)n_in; (void)out_size;

    cudaFuncSetAttribute(k_gemm, cudaFuncAttributeMaxDynamicSharedMemorySize, 2 * STAGEB);

    k_nbr<<<NV, 128>>>(adj);
    k_cr<<<NV / 4, 128>>>();
    k_a2<<<NV, 256>>>();
    k_gemm<<<528, 256, 2 * STAGEB>>>();
    k_top8<<<NV, 128>>>();
    k_embed<<<NV / 8, 256>>>(ew, eb);
    k_layer<<<NV / 8, 256>>>(0, w1 + 0*4096, b1 + 0*64, w2 + 0*4096, b2 + 0*64, eps + 0);
    k_layer<<<NV / 8, 256>>>(1, w1 + 1*4096, b1 + 1*64, w2 + 1*4096, b2 + 1*64, eps + 1);
    k_layer<<<NV / 8, 256>>>(0, w1 + 2*4096, b1 + 2*64, w2 + 2*4096, b2 + 2*64, eps + 2);
    k_colsum<<<64, 256>>>(out);
}